// round 8
// baseline (speedup 1.0000x reference)
#include <cuda_runtime.h>
#include <cuda_bf16.h>

#define BB 16
#define NN 256
#define DD 512
#define PE_ROWS 64   // pos = t - start < x[b,seg] <= 63 -> pos in [0,62]

// Persistent kernel, 2 CTAs/SM (64 warps/SM). smem holds ONLY the 16 KB
// per-batch cumsum table; the 128 KB hot pos_enc set (rows 0..63) lives in
// L1D (228 KB) via __ldg. Warps own contiguous row ranges: binary search
// once, monotone segment advance, 4x LDG.128 (L1-hit) -> 4x STG.128 per row.
// Invalid rows store a register zero (no load).
__global__ __launch_bounds__(1024, 2)
void pe_gather_kernel(const int* __restrict__ x,
                      const float* __restrict__ pos_enc,
                      float* __restrict__ out, int T, int chunk) {
    __shared__ int s_cum[BB * NN];                      // 16 KB

    const int warp = threadIdx.x >> 5;
    const int lane = threadIdx.x & 31;

    // ---- per-CTA cumsum of x: warps 0..15 each scan one batch row ----
    if (warp < BB) {
        int carry = 0;
        for (int c = 0; c < NN / 32; c++) {
            int idx = c * 32 + lane;
            int v = x[warp * NN + idx];
            #pragma unroll
            for (int off = 1; off < 32; off <<= 1) {
                int n = __shfl_up_sync(0xffffffffu, v, off);
                if (lane >= off) v += n;
            }
            v += carry;
            s_cum[warp * NN + idx] = v;
            carry = __shfl_sync(0xffffffffu, v, 31);
        }
    }
    __syncthreads();

    // ---- contiguous row range for this warp ----
    const long total = (long)BB * T;
    const int warp_global = blockIdx.x * (blockDim.x >> 5) + warp;
    long r0 = (long)warp_global * chunk;
    if (r0 >= total) return;
    long r1 = r0 + chunk; if (r1 > total) r1 = total;

    int b = (int)(r0 / T);            // only division in the kernel
    int t = (int)(r0 - (long)b * T);
    const int* cum = s_cum + b * NN;
    int last = cum[NN - 1];

    // searchsorted(cum, t, 'right'): first seg with cum[seg] > t (257 answers -> 9 steps)
    int seg;
    {
        int lo = 0, hi = NN;
        #pragma unroll
        for (int it = 0; it < 9; it++) {
            if (lo < hi) {
                int mid = (lo + hi) >> 1;
                if (cum[mid] <= t) lo = mid + 1; else hi = mid;
            }
        }
        seg = lo;
    }

    const float4 z = make_float4(0.f, 0.f, 0.f, 0.f);

    for (long r = r0; r < r1; r++) {
        float4* dst = (float4*)(out + r * (long)DD);

        if (t >= last) {
            // past this batch-row's total frames -> zeros from registers
            dst[lane +  0] = z;
            dst[lane + 32] = z;
            dst[lane + 64] = z;
            dst[lane + 96] = z;
        } else {
            while (cum[seg] <= t) seg++;                 // monotone advance
            const int start = (seg > 0) ? cum[seg - 1] : 0;
            const int pos = t - start;                   // [0, 62]
            const float4* src = (const float4*)(pos_enc + pos * DD);
            // 4 independent L1-resident loads (128 KB hot set fits in L1D)
            float4 v0 = __ldg(src + lane +  0);
            float4 v1 = __ldg(src + lane + 32);
            float4 v2 = __ldg(src + lane + 64);
            float4 v3 = __ldg(src + lane + 96);
            dst[lane +  0] = v0;
            dst[lane + 32] = v1;
            dst[lane + 64] = v2;
            dst[lane + 96] = v3;
        }

        if (++t == T) {                                  // batch-row boundary
            t = 0; b++;
            if (b < BB) { cum += NN; last = cum[NN - 1]; seg = 0; }
            else break;
        }
    }
}

extern "C" void kernel_launch(void* const* d_in, const int* in_sizes, int n_in,
                              void* d_out, int out_size) {
    const int*   x       = (const int*)d_in[0];
    const float* pos_enc = (const float*)d_in[1];
    float*       out     = (float*)d_out;

    const int T = out_size / (BB * DD);

    int sms = 148;
    cudaDeviceGetAttribute(&sms, cudaDevAttrMultiProcessorCount, 0);

    const int nctas = sms * 2;                           // 2 CTAs/SM -> 64 warps/SM
    const long total = (long)BB * T;
    const int nwarps = nctas * 32;
    const int chunk = (int)((total + nwarps - 1) / nwarps);

    pe_gather_kernel<<<nctas, 1024>>>(x, pos_enc, out, T, chunk);
}

// round 10
// speedup vs baseline: 1.0446x; 1.0446x over previous
#include <cuda_runtime.h>
#include <cuda_bf16.h>

#define BB 16
#define NN 256
#define DD 512
#define PE_ROWS 64   // pos = t - start < x[b,seg] <= 63 -> pos in [0,62]

// Final-form persistent kernel (write-path-ceiling bound, ~5.9 TB/s effective).
// Each CTA stages pos_enc rows 0..63 (128 KB) + per-batch cumsum (16 KB) in
// smem. Warps own CONTIGUOUS row ranges: one binary search, then monotone
// segment advance (1 smem broadcast/row). 4x LDS.128 -> 4x STG.128 with
// DEFAULT cache policy (L2 write-back absorbs ~50 MB/replay; .cs defeats it).
// Tail rows store register zeros (no load).
__global__ __launch_bounds__(1024, 1)
void pe_gather_kernel(const int* __restrict__ x,
                      const float* __restrict__ pos_enc,
                      float* __restrict__ out, int T, int chunk) {
    extern __shared__ float smem[];
    float* s_pe  = smem;                                // PE_ROWS*DD floats (128 KB)
    int*   s_cum = (int*)(smem + PE_ROWS * DD);         // BB*NN ints (16 KB)

    const int warp = threadIdx.x >> 5;
    const int lane = threadIdx.x & 31;

    // ---- stage hot pos_enc rows (hits L2 after first CTA) ----
    {
        const float4* src = (const float4*)pos_enc;
        float4* dst = (float4*)s_pe;
        for (int i = threadIdx.x; i < PE_ROWS * DD / 4; i += blockDim.x)
            dst[i] = src[i];
    }

    // ---- per-CTA cumsum of x: warps 0..15 each scan one batch row ----
    if (warp < BB) {
        int carry = 0;
        for (int c = 0; c < NN / 32; c++) {
            int idx = c * 32 + lane;
            int v = x[warp * NN + idx];
            #pragma unroll
            for (int off = 1; off < 32; off <<= 1) {
                int n = __shfl_up_sync(0xffffffffu, v, off);
                if (lane >= off) v += n;
            }
            v += carry;
            s_cum[warp * NN + idx] = v;
            carry = __shfl_sync(0xffffffffu, v, 31);
        }
    }
    __syncthreads();

    // ---- contiguous row range for this warp ----
    const long total = (long)BB * T;
    const int warp_global = blockIdx.x * (blockDim.x >> 5) + warp;
    long r0 = (long)warp_global * chunk;
    if (r0 >= total) return;
    long r1 = r0 + chunk; if (r1 > total) r1 = total;

    int b = (int)(r0 / T);            // only division in the kernel
    int t = (int)(r0 - (long)b * T);
    const int* cum = s_cum + b * NN;
    int last = cum[NN - 1];

    // searchsorted(cum, t, 'right'): first seg with cum[seg] > t (257 answers -> 9 steps)
    int seg;
    {
        int lo = 0, hi = NN;
        #pragma unroll
        for (int it = 0; it < 9; it++) {
            if (lo < hi) {
                int mid = (lo + hi) >> 1;
                if (cum[mid] <= t) lo = mid + 1; else hi = mid;
            }
        }
        seg = lo;
    }

    const float4 z = make_float4(0.f, 0.f, 0.f, 0.f);

    for (long r = r0; r < r1; r++) {
        float4* dst = (float4*)(out + r * (long)DD);

        if (t >= last) {
            // past this batch-row's total frames -> zeros from registers
            dst[lane +  0] = z;
            dst[lane + 32] = z;
            dst[lane + 64] = z;
            dst[lane + 96] = z;
        } else {
            while (cum[seg] <= t) seg++;                 // monotone advance
            const int start = (seg > 0) ? cum[seg - 1] : 0;
            const int pos = t - start;                   // [0, 62]
            const float4* src = (const float4*)(s_pe + pos * DD);
            float4 v0 = src[lane +  0];
            float4 v1 = src[lane + 32];
            float4 v2 = src[lane + 64];
            float4 v3 = src[lane + 96];
            dst[lane +  0] = v0;
            dst[lane + 32] = v1;
            dst[lane + 64] = v2;
            dst[lane + 96] = v3;
        }

        if (++t == T) {                                  // batch-row boundary
            t = 0; b++;
            if (b < BB) { cum += NN; last = cum[NN - 1]; seg = 0; }
            else break;
        }
    }
}

extern "C" void kernel_launch(void* const* d_in, const int* in_sizes, int n_in,
                              void* d_out, int out_size) {
    const int*   x       = (const int*)d_in[0];
    const float* pos_enc = (const float*)d_in[1];
    float*       out     = (float*)d_out;

    const int T = out_size / (BB * DD);

    int sms = 148;
    cudaDeviceGetAttribute(&sms, cudaDevAttrMultiProcessorCount, 0);

    const long total = (long)BB * T;
    const int nwarps = sms * 32;
    const int chunk = (int)((total + nwarps - 1) / nwarps);

    const size_t smem_bytes = (size_t)(PE_ROWS * DD) * sizeof(float)
                            + (size_t)(BB * NN) * sizeof(int);   // 147456 B
    cudaFuncSetAttribute(pe_gather_kernel,
                         cudaFuncAttributeMaxDynamicSharedMemorySize,
                         (int)smem_bytes);
    pe_gather_kernel<<<sms, 1024, smem_bytes>>>(x, pos_enc, out, T, chunk);
}

// round 11
// speedup vs baseline: 1.0530x; 1.0081x over previous
#include <cuda_runtime.h>
#include <cuda_bf16.h>

#define BB 16
#define NN 256
#define DD 512
#define PE_ROWS 64   // pos = t - start < x[b,seg] <= 63 -> pos in [0,62]

// 256-bit global stores (sm_100+): one instruction commits 1 KB/warp.
__device__ __forceinline__ void stg256(float* p, float4 a, float4 b) {
    asm volatile("st.global.v8.f32 [%0], {%1,%2,%3,%4,%5,%6,%7,%8};"
                 :: "l"(p), "f"(a.x), "f"(a.y), "f"(a.z), "f"(a.w),
                    "f"(b.x), "f"(b.y), "f"(b.z), "f"(b.w)
                 : "memory");
}

// Persistent kernel, write-wall bound (~4.75 TB/s DRAM). Each CTA stages
// pos_enc rows 0..63 (128 KB) + per-batch cumsum (16 KB) in smem. Warps own
// CONTIGUOUS row ranges: one binary search, monotone segment advance, then
// per row 4x LDS.128 -> 2x STG.256 (1 KB/warp per store instruction, plain
// write-back policy). Tail rows store register zeros.
__global__ __launch_bounds__(1024, 1)
void pe_gather_kernel(const int* __restrict__ x,
                      const float* __restrict__ pos_enc,
                      float* __restrict__ out, int T, int chunk) {
    extern __shared__ float smem[];
    float* s_pe  = smem;                                // PE_ROWS*DD floats (128 KB)
    int*   s_cum = (int*)(smem + PE_ROWS * DD);         // BB*NN ints (16 KB)

    const int warp = threadIdx.x >> 5;
    const int lane = threadIdx.x & 31;

    // ---- stage hot pos_enc rows (L2-resident after first CTA) ----
    {
        const float4* src = (const float4*)pos_enc;
        float4* dst = (float4*)s_pe;
        for (int i = threadIdx.x; i < PE_ROWS * DD / 4; i += blockDim.x)
            dst[i] = src[i];
    }

    // ---- per-CTA cumsum of x: warps 0..15 each scan one batch row ----
    if (warp < BB) {
        int carry = 0;
        for (int c = 0; c < NN / 32; c++) {
            int idx = c * 32 + lane;
            int v = x[warp * NN + idx];
            #pragma unroll
            for (int off = 1; off < 32; off <<= 1) {
                int n = __shfl_up_sync(0xffffffffu, v, off);
                if (lane >= off) v += n;
            }
            v += carry;
            s_cum[warp * NN + idx] = v;
            carry = __shfl_sync(0xffffffffu, v, 31);
        }
    }
    __syncthreads();

    // ---- contiguous row range for this warp ----
    const long total = (long)BB * T;
    const int warp_global = blockIdx.x * (blockDim.x >> 5) + warp;
    long r0 = (long)warp_global * chunk;
    if (r0 >= total) return;
    long r1 = r0 + chunk; if (r1 > total) r1 = total;

    int b = (int)(r0 / T);            // only division in the kernel
    int t = (int)(r0 - (long)b * T);
    const int* cum = s_cum + b * NN;
    int last = cum[NN - 1];

    // searchsorted(cum, t, 'right'): first seg with cum[seg] > t (257 answers -> 9 steps)
    int seg;
    {
        int lo = 0, hi = NN;
        #pragma unroll
        for (int it = 0; it < 9; it++) {
            if (lo < hi) {
                int mid = (lo + hi) >> 1;
                if (cum[mid] <= t) lo = mid + 1; else hi = mid;
            }
        }
        seg = lo;
    }

    const float4 z = make_float4(0.f, 0.f, 0.f, 0.f);

    for (long r = r0; r < r1; r++) {
        // lane l owns floats [8l, 8l+8) and [256+8l, 256+8l+8) of the row
        float* dst = out + r * (long)DD + lane * 8;

        if (t >= last) {
            stg256(dst,       z, z);
            stg256(dst + 256, z, z);
        } else {
            while (cum[seg] <= t) seg++;                 // monotone advance
            const int start = (seg > 0) ? cum[seg - 1] : 0;
            const int pos = t - start;                   // [0, 62]
            const float4* src = (const float4*)(s_pe + pos * DD) + lane * 2;
            float4 v0 = src[0];
            float4 v1 = src[1];
            float4 v2 = src[64];     // +256 floats
            float4 v3 = src[65];
            stg256(dst,       v0, v1);
            stg256(dst + 256, v2, v3);
        }

        if (++t == T) {                                  // batch-row boundary
            t = 0; b++;
            if (b < BB) { cum += NN; last = cum[NN - 1]; seg = 0; }
            else break;
        }
    }
}

extern "C" void kernel_launch(void* const* d_in, const int* in_sizes, int n_in,
                              void* d_out, int out_size) {
    const int*   x       = (const int*)d_in[0];
    const float* pos_enc = (const float*)d_in[1];
    float*       out     = (float*)d_out;

    const int T = out_size / (BB * DD);

    int sms = 148;
    cudaDeviceGetAttribute(&sms, cudaDevAttrMultiProcessorCount, 0);

    const long total = (long)BB * T;
    const int nwarps = sms * 32;
    const int chunk = (int)((total + nwarps - 1) / nwarps);

    const size_t smem_bytes = (size_t)(PE_ROWS * DD) * sizeof(float)
                            + (size_t)(BB * NN) * sizeof(int);   // 147456 B
    cudaFuncSetAttribute(pe_gather_kernel,
                         cudaFuncAttributeMaxDynamicSharedMemorySize,
                         (int)smem_bytes);
    pe_gather_kernel<<<sms, 1024, smem_bytes>>>(x, pos_enc, out, T, chunk);
}